// round 12
// baseline (speedup 1.0000x reference)
#include <cuda_runtime.h>
#include <cuda_bf16.h>

// Chamfer distance via PRE-GATHERED neighborhood lists — 2 kernels.
// B=2, N=M=8192, C=3, coords ~U[0,1).
//
//  K1 insert27: each (point, one of its <=27 in-bounds neighbor cells) pair is
//     one thread: 1 atomic + 1 st.128 into that cell's NEIGHBORHOOD list.
//     The s==13 (center) copy also maintains the base per-cell list used by
//     the rare expansion fallback. Overflows -> per-set list.
//  K2 query: one thread per query. Load q, ONE count, then STREAM the
//     cell's neighborhood list (contiguous float4s, affine addresses, high
//     MLP) + (normally empty) overflow list. r=1 bound check; rare miss ->
//     serial ring expansion over base cells. Register-accumulate direction
//     sums; per-CTA partials; last-arriving CTA finalizes + re-zeros counts.
//
// Determinism: fixed thread->query mapping; fixed-order sums; atomic slot
// permutations only feed fminf (permutation-invariant) -> bitwise
// deterministic. Scratch (counts, overflow, done) restored every run ->
// graph-replay invariant.

#define G        16
#define NC       (G * G * G)
#define CAP      16            // base per-cell capacity (fallback path)
#define CAP2     112           // neighborhood list capacity (~54 expected)
#define OVF_CAP  256
#define B_MAX    4
#define NSETS_MAX 8
#define BLK      128
#define MAXBLK   4096

__device__ int    g_cnt  [NSETS_MAX * NC];                 // static zero; restored
__device__ float4 g_cell [NSETS_MAX * NC * CAP];
__device__ int    g_nbcnt[NSETS_MAX * NC];                 // static zero; restored
__device__ float4 g_nb   [NSETS_MAX * NC * CAP2];          // ~59MB static
__device__ int    g_ovf_cnt[NSETS_MAX];                    // static zero; restored
__device__ float4 g_ovf  [NSETS_MAX * OVF_CAP];
__device__ float  g_p0[MAXBLK], g_p1[MAXBLK];
__device__ unsigned int g_done = 0;

__device__ __forceinline__ int cell_of(float v) {
    int c = (int)(v * (float)G);
    return min(max(c, 0), G - 1);
}

// grid: (ceil(maxP/BLK), nsets, 27)
__global__ __launch_bounds__(BLK)
void insert27_kernel(const float* __restrict__ pos,
                     const float* __restrict__ xhat,
                     int N, int M, int B) {
    const int sid   = blockIdx.y;
    const int s     = blockIdx.z;               // neighbor offset id 0..26
    const int cloud = sid / B;
    const int b     = sid % B;
    const int n     = cloud ? M : N;
    const int i     = blockIdx.x * BLK + threadIdx.x;
    if (i >= n) return;

    const float* p = (cloud ? xhat : pos) + ((size_t)b * n + i) * 3;
    const float x = p[0], y = p[1], z = p[2];
    const int cx = cell_of(x), cy = cell_of(y), cz = cell_of(z);

    const int tx = cx + (s % 3) - 1;
    const int ty = cy + ((s / 3) % 3) - 1;
    const int tz = cz + (s / 9) - 1;

    const float4 v = make_float4(x, y, z, x * x + y * y + z * z);

    if (s == 13) {   // center copy: maintain base per-cell list for fallback
        const int c = (cz * G + cy) * G + cx;
        const int slot = atomicAdd(&g_cnt[sid * NC + c], 1);
        if (slot < CAP) {
            g_cell[(sid * NC + c) * CAP + slot] = v;
        } else {
            const int o = atomicAdd(&g_ovf_cnt[sid], 1);
            if (o < OVF_CAP) g_ovf[sid * OVF_CAP + o] = v;
        }
    }

    if (tx < 0 || tx >= G || ty < 0 || ty >= G || tz < 0 || tz >= G) return;
    const int c = (tz * G + ty) * G + tx;
    const int slot = atomicAdd(&g_nbcnt[sid * NC + c], 1);
    if (slot < CAP2) {
        g_nb[((size_t)(sid * NC + c)) * CAP2 + slot] = v;
    } else {
        const int o = atomicAdd(&g_ovf_cnt[sid], 1);
        if (o < OVF_CAP) g_ovf[sid * OVF_CAP + o] = v;
    }
}

// grid: (ceil(maxP/BLK), nsets)   one thread per query; finalize fused
__global__ __launch_bounds__(BLK)
void query_kernel(const float* __restrict__ pos,
                  const float* __restrict__ xhat,
                  float* __restrict__ out, int out_size,
                  int N, int M, int B) {
    const int yb  = blockIdx.y;          // dir*B + b
    const int dir = yb / B;
    const int b   = yb % B;
    const int nQ  = dir ? M : N;
    const int i   = blockIdx.x * BLK + threadIdx.x;

    float acc0 = 0.f, acc1 = 0.f;

    if (i < nQ) {
        const int sid_t = (1 - dir) * B + b;   // target = other cloud

        const float* qp = (dir ? xhat : pos) + ((size_t)b * nQ + i) * 3;
        const float qx = qp[0], qy = qp[1], qz = qp[2];
        const float qn = qx * qx + qy * qy + qz * qz;
        const float m2x = -2.0f * qx, m2y = -2.0f * qy, m2z = -2.0f * qz;
        const int cx = cell_of(qx), cy = cell_of(qy), cz = cell_of(qz);
        const int c  = (cz * G + cy) * G + cx;

        // ---- stream the pre-gathered neighborhood list ----
        const int nc = min(g_nbcnt[sid_t * NC + c], CAP2);
        const float4* __restrict__ lst = g_nb + ((size_t)(sid_t * NC + c)) * CAP2;

        float mA = 3.4e38f, mB2 = 3.4e38f, mC = 3.4e38f, mD = 3.4e38f;
        int k = 0;
        for (; k + 4 <= nc; k += 4) {
            const float4 t0 = lst[k + 0];
            const float4 t1 = lst[k + 1];
            const float4 t2 = lst[k + 2];
            const float4 t3 = lst[k + 3];
            mA  = fminf(mA,  fmaf(m2x, t0.x, fmaf(m2y, t0.y, fmaf(m2z, t0.z, t0.w))));
            mB2 = fminf(mB2, fmaf(m2x, t1.x, fmaf(m2y, t1.y, fmaf(m2z, t1.z, t1.w))));
            mC  = fminf(mC,  fmaf(m2x, t2.x, fmaf(m2y, t2.y, fmaf(m2z, t2.z, t2.w))));
            mD  = fminf(mD,  fmaf(m2x, t3.x, fmaf(m2y, t3.y, fmaf(m2z, t3.z, t3.w))));
        }
        for (; k < nc; ++k) {
            const float4 t0 = lst[k];
            mA = fminf(mA, fmaf(m2x, t0.x, fmaf(m2y, t0.y, fmaf(m2z, t0.z, t0.w))));
        }
        float minAcc = fminf(fminf(mA, mB2), fminf(mC, mD));

        // ---- overflow list (normally empty) ----
        {
            const int no = min(g_ovf_cnt[sid_t], OVF_CAP);
            for (int t = 0; t < no; ++t) {
                const float4 tt = g_ovf[sid_t * OVF_CAP + t];
                minAcc = fminf(minAcc,
                    fmaf(m2x, tt.x, fmaf(m2y, tt.y, fmaf(m2z, tt.z, tt.w))));
            }
        }

        // ---- r=1 termination bound; rare miss -> serial expansion ----
        const float h = 1.0f / (float)G;
        const int x0 = max(cx - 1, 0), x1 = min(cx + 1, G - 1);
        const int y0 = max(cy - 1, 0), y1 = min(cy + 1, G - 1);
        const int z0 = max(cz - 1, 0), z1 = min(cz + 1, G - 1);
        float db = 3.4e38f;
        if (x0 > 0)     db = fminf(db, qx - (float)x0 * h);
        if (x1 < G - 1) db = fminf(db, (float)(x1 + 1) * h - qx);
        if (y0 > 0)     db = fminf(db, qy - (float)y0 * h);
        if (y1 < G - 1) db = fminf(db, (float)(y1 + 1) * h - qy);
        if (z0 > 0)     db = fminf(db, qz - (float)z0 * h);
        if (z1 < G - 1) db = fminf(db, (float)(z1 + 1) * h - qz);

        if ((qn + minAcc) > db * db) {
            const int*    __restrict__ cnt  = g_cnt  + sid_t * NC;
            const float4* __restrict__ cell = g_cell + (size_t)sid_t * NC * CAP;
            int r = 2;
            while (true) {
                const int ex0 = max(cx - r, 0), ex1 = min(cx + r, G - 1);
                const int ey0 = max(cy - r, 0), ey1 = min(cy + r, G - 1);
                const int ez0 = max(cz - r, 0), ez1 = min(cz + r, G - 1);
                for (int z = ez0; z <= ez1; ++z)
                    for (int y = ey0; y <= ey1; ++y)
                        for (int x = ex0; x <= ex1; ++x) {
                            const int cc = (z * G + y) * G + x;
                            const int n2 = min(cnt[cc], CAP);
                            for (int t = 0; t < n2; ++t) {
                                const float4 tt = cell[cc * CAP + t];
                                minAcc = fminf(minAcc,
                                    fmaf(m2x, tt.x,
                                    fmaf(m2y, tt.y,
                                    fmaf(m2z, tt.z, tt.w))));
                            }
                        }
                float edb = 3.4e38f;
                if (ex0 > 0)     edb = fminf(edb, qx - (float)ex0 * h);
                if (ex1 < G - 1) edb = fminf(edb, (float)(ex1 + 1) * h - qx);
                if (ey0 > 0)     edb = fminf(edb, qy - (float)ey0 * h);
                if (ey1 < G - 1) edb = fminf(edb, (float)(ey1 + 1) * h - qy);
                if (ez0 > 0)     edb = fminf(edb, qz - (float)ez0 * h);
                if (ez1 < G - 1) edb = fminf(edb, (float)(ez1 + 1) * h - qz);
                const bool ef = (ex0 == 0 && ey0 == 0 && ez0 == 0 &&
                                 ex1 == G - 1 && ey1 == G - 1 && ez1 == G - 1);
                if (ef || (qn + minAcc) <= edb * edb) break;
                ++r;
            }
        }

        const float dist = fmaxf(qn + minAcc, 0.0f);
        if (dir == 0) acc0 = dist; else acc1 = dist;
    }

    // ---- deterministic per-block partials ----
    __shared__ float red0[BLK / 32], red1[BLK / 32];
    __shared__ bool  amLast;
#pragma unroll
    for (int o = 16; o > 0; o >>= 1) {
        acc0 += __shfl_xor_sync(0xffffffffu, acc0, o);
        acc1 += __shfl_xor_sync(0xffffffffu, acc1, o);
    }
    if ((threadIdx.x & 31) == 0) {
        red0[threadIdx.x >> 5] = acc0;
        red1[threadIdx.x >> 5] = acc1;
    }
    __syncthreads();
    if (threadIdx.x == 0) {
        float s0 = 0.f, s1 = 0.f;
#pragma unroll
        for (int w = 0; w < BLK / 32; ++w) { s0 += red0[w]; s1 += red1[w]; }
        const int bid = blockIdx.y * gridDim.x + blockIdx.x;
        g_p0[bid] = s0;
        g_p1[bid] = s1;
        __threadfence();                                    // release partials
        amLast = (atomicAdd(&g_done, 1u) == gridDim.x * gridDim.y - 1);
    }
    __syncthreads();

    // ---- last-arriving CTA: finalize + restore scratch ----
    if (amLast) {
        __threadfence();                                    // acquire partials
        const int nb = gridDim.x * gridDim.y;
        float s0 = 0.f, s1 = 0.f;
        for (int t = threadIdx.x; t < nb; t += BLK) {
            s0 += g_p0[t];
            s1 += g_p1[t];
        }
#pragma unroll
        for (int o = 16; o > 0; o >>= 1) {
            s0 += __shfl_xor_sync(0xffffffffu, s0, o);
            s1 += __shfl_xor_sync(0xffffffffu, s1, o);
        }
        if ((threadIdx.x & 31) == 0) {
            red0[threadIdx.x >> 5] = s0;
            red1[threadIdx.x >> 5] = s1;
        }
        __syncthreads();

        // restore scratch for next graph replay
        {
            const int nsets = 2 * B;
            int4* cp = (int4*)g_cnt;
            int4* np = (int4*)g_nbcnt;
            const int n4 = (nsets * NC) >> 2;
            for (int t = threadIdx.x; t < n4; t += BLK) {
                cp[t] = make_int4(0, 0, 0, 0);
                np[t] = make_int4(0, 0, 0, 0);
            }
            if (threadIdx.x < NSETS_MAX) g_ovf_cnt[threadIdx.x] = 0;
        }

        if (threadIdx.x == 0) {
            float t0 = 0.f, t1 = 0.f;
#pragma unroll
            for (int w = 0; w < BLK / 32; ++w) { t0 += red0[w]; t1 += red1[w]; }
            g_done = 0;
            const float rec = t0 / (float)((size_t)B * N) + t1 / (float)((size_t)B * M);
            for (int t = 0; t < out_size; ++t) out[t] = rec;  // (loss, rec_loss)
        }
    }
}

extern "C" void kernel_launch(void* const* d_in, const int* in_sizes, int n_in,
                              void* d_out, int out_size) {
    const float* pos  = (const float*)d_in[0];
    const float* xhat = (const float*)d_in[1];

    const int B = 2;
    const int N = in_sizes[0] / (B * 3);
    const int M = in_sizes[1] / (B * 3);
    const int nsets = 2 * B;
    const int maxP  = (N > M) ? N : M;
    const int nbx   = (maxP + BLK - 1) / BLK;

    {   // K1: one thread per (point, neighbor-offset)
        dim3 g(nbx, nsets, 27);
        insert27_kernel<<<g, BLK>>>(pos, xhat, N, M, B);
    }
    {   // K2: one thread per query (+fused finalize)
        dim3 g(nbx, nsets);
        query_kernel<<<g, BLK>>>(pos, xhat, (float*)d_out, out_size, N, M, B);
    }
}

// round 13
// speedup vs baseline: 1.3693x; 1.3693x over previous
#include <cuda_runtime.h>
#include <cuda_bf16.h>

// Chamfer distance via PRE-GATHERED neighborhood lists — 2 kernels.
// B=2, N=M=8192, C=3, coords ~U[0,1).
//
//  K1 insert27: each (point, one of its <=27 in-bounds neighbor cells) pair is
//     one thread: 1 atomic + 1 st.128 into that cell's NEIGHBORHOOD list.
//     The s==13 (center) copy also maintains the base per-cell list used by
//     the rare expansion fallback. Overflows -> per-set list.
//  K2 query: one thread per query. Load q, ONE count, then STREAM the
//     cell's neighborhood list (contiguous float4s, affine addresses, high
//     MLP) + (normally empty) overflow list. r=1 bound check; rare miss ->
//     serial ring expansion over base cells. Register-accumulate direction
//     sums; per-CTA partials; last-arriving CTA finalizes + re-zeros counts.
//
// Determinism: fixed thread->query mapping; fixed-order sums; atomic slot
// permutations only feed fminf (permutation-invariant) -> bitwise
// deterministic. Scratch (counts, overflow, done) restored every run ->
// graph-replay invariant.

#define G        16
#define NC       (G * G * G)
#define CAP      16            // base per-cell capacity (fallback path)
#define CAP2     112           // neighborhood list capacity (~54 expected)
#define OVF_CAP  256
#define B_MAX    4
#define NSETS_MAX 8
#define BLK      128
#define MAXBLK   4096

__device__ int    g_cnt  [NSETS_MAX * NC];                 // static zero; restored
__device__ float4 g_cell [NSETS_MAX * NC * CAP];
__device__ int    g_nbcnt[NSETS_MAX * NC];                 // static zero; restored
__device__ float4 g_nb   [NSETS_MAX * NC * CAP2];          // ~59MB static
__device__ int    g_ovf_cnt[NSETS_MAX];                    // static zero; restored
__device__ float4 g_ovf  [NSETS_MAX * OVF_CAP];
__device__ float  g_p0[MAXBLK], g_p1[MAXBLK];
__device__ unsigned int g_done = 0;

__device__ __forceinline__ int cell_of(float v) {
    int c = (int)(v * (float)G);
    return min(max(c, 0), G - 1);
}

// grid: (ceil(maxP/BLK), nsets, 27)
__global__ __launch_bounds__(BLK)
void insert27_kernel(const float* __restrict__ pos,
                     const float* __restrict__ xhat,
                     int N, int M, int B) {
    const int sid   = blockIdx.y;
    const int s     = blockIdx.z;               // neighbor offset id 0..26
    const int cloud = sid / B;
    const int b     = sid % B;
    const int n     = cloud ? M : N;
    const int i     = blockIdx.x * BLK + threadIdx.x;
    if (i >= n) return;

    const float* p = (cloud ? xhat : pos) + ((size_t)b * n + i) * 3;
    const float x = p[0], y = p[1], z = p[2];
    const int cx = cell_of(x), cy = cell_of(y), cz = cell_of(z);

    const int tx = cx + (s % 3) - 1;
    const int ty = cy + ((s / 3) % 3) - 1;
    const int tz = cz + (s / 9) - 1;

    const float4 v = make_float4(x, y, z, x * x + y * y + z * z);

    if (s == 13) {   // center copy: maintain base per-cell list for fallback
        const int c = (cz * G + cy) * G + cx;
        const int slot = atomicAdd(&g_cnt[sid * NC + c], 1);
        if (slot < CAP) {
            g_cell[(sid * NC + c) * CAP + slot] = v;
        } else {
            const int o = atomicAdd(&g_ovf_cnt[sid], 1);
            if (o < OVF_CAP) g_ovf[sid * OVF_CAP + o] = v;
        }
    }

    if (tx < 0 || tx >= G || ty < 0 || ty >= G || tz < 0 || tz >= G) return;
    const int c = (tz * G + ty) * G + tx;
    const int slot = atomicAdd(&g_nbcnt[sid * NC + c], 1);
    if (slot < CAP2) {
        g_nb[((size_t)(sid * NC + c)) * CAP2 + slot] = v;
    } else {
        const int o = atomicAdd(&g_ovf_cnt[sid], 1);
        if (o < OVF_CAP) g_ovf[sid * OVF_CAP + o] = v;
    }
}

// grid: (ceil(maxP/BLK), nsets)   one thread per query; finalize fused
__global__ __launch_bounds__(BLK)
void query_kernel(const float* __restrict__ pos,
                  const float* __restrict__ xhat,
                  float* __restrict__ out, int out_size,
                  int N, int M, int B) {
    const int yb  = blockIdx.y;          // dir*B + b
    const int dir = yb / B;
    const int b   = yb % B;
    const int nQ  = dir ? M : N;
    const int i   = blockIdx.x * BLK + threadIdx.x;

    float acc0 = 0.f, acc1 = 0.f;

    if (i < nQ) {
        const int sid_t = (1 - dir) * B + b;   // target = other cloud

        const float* qp = (dir ? xhat : pos) + ((size_t)b * nQ + i) * 3;
        const float qx = qp[0], qy = qp[1], qz = qp[2];
        const float qn = qx * qx + qy * qy + qz * qz;
        const float m2x = -2.0f * qx, m2y = -2.0f * qy, m2z = -2.0f * qz;
        const int cx = cell_of(qx), cy = cell_of(qy), cz = cell_of(qz);
        const int c  = (cz * G + cy) * G + cx;

        // ---- stream the pre-gathered neighborhood list ----
        const int nc = min(g_nbcnt[sid_t * NC + c], CAP2);
        const float4* __restrict__ lst = g_nb + ((size_t)(sid_t * NC + c)) * CAP2;

        float mA = 3.4e38f, mB2 = 3.4e38f, mC = 3.4e38f, mD = 3.4e38f;
        int k = 0;
        for (; k + 4 <= nc; k += 4) {
            const float4 t0 = lst[k + 0];
            const float4 t1 = lst[k + 1];
            const float4 t2 = lst[k + 2];
            const float4 t3 = lst[k + 3];
            mA  = fminf(mA,  fmaf(m2x, t0.x, fmaf(m2y, t0.y, fmaf(m2z, t0.z, t0.w))));
            mB2 = fminf(mB2, fmaf(m2x, t1.x, fmaf(m2y, t1.y, fmaf(m2z, t1.z, t1.w))));
            mC  = fminf(mC,  fmaf(m2x, t2.x, fmaf(m2y, t2.y, fmaf(m2z, t2.z, t2.w))));
            mD  = fminf(mD,  fmaf(m2x, t3.x, fmaf(m2y, t3.y, fmaf(m2z, t3.z, t3.w))));
        }
        for (; k < nc; ++k) {
            const float4 t0 = lst[k];
            mA = fminf(mA, fmaf(m2x, t0.x, fmaf(m2y, t0.y, fmaf(m2z, t0.z, t0.w))));
        }
        float minAcc = fminf(fminf(mA, mB2), fminf(mC, mD));

        // ---- overflow list (normally empty) ----
        {
            const int no = min(g_ovf_cnt[sid_t], OVF_CAP);
            for (int t = 0; t < no; ++t) {
                const float4 tt = g_ovf[sid_t * OVF_CAP + t];
                minAcc = fminf(minAcc,
                    fmaf(m2x, tt.x, fmaf(m2y, tt.y, fmaf(m2z, tt.z, tt.w))));
            }
        }

        // ---- r=1 termination bound; rare miss -> serial expansion ----
        const float h = 1.0f / (float)G;
        const int x0 = max(cx - 1, 0), x1 = min(cx + 1, G - 1);
        const int y0 = max(cy - 1, 0), y1 = min(cy + 1, G - 1);
        const int z0 = max(cz - 1, 0), z1 = min(cz + 1, G - 1);
        float db = 3.4e38f;
        if (x0 > 0)     db = fminf(db, qx - (float)x0 * h);
        if (x1 < G - 1) db = fminf(db, (float)(x1 + 1) * h - qx);
        if (y0 > 0)     db = fminf(db, qy - (float)y0 * h);
        if (y1 < G - 1) db = fminf(db, (float)(y1 + 1) * h - qy);
        if (z0 > 0)     db = fminf(db, qz - (float)z0 * h);
        if (z1 < G - 1) db = fminf(db, (float)(z1 + 1) * h - qz);

        if ((qn + minAcc) > db * db) {
            const int*    __restrict__ cnt  = g_cnt  + sid_t * NC;
            const float4* __restrict__ cell = g_cell + (size_t)sid_t * NC * CAP;
            int r = 2;
            while (true) {
                const int ex0 = max(cx - r, 0), ex1 = min(cx + r, G - 1);
                const int ey0 = max(cy - r, 0), ey1 = min(cy + r, G - 1);
                const int ez0 = max(cz - r, 0), ez1 = min(cz + r, G - 1);
                for (int z = ez0; z <= ez1; ++z)
                    for (int y = ey0; y <= ey1; ++y)
                        for (int x = ex0; x <= ex1; ++x) {
                            const int cc = (z * G + y) * G + x;
                            const int n2 = min(cnt[cc], CAP);
                            for (int t = 0; t < n2; ++t) {
                                const float4 tt = cell[cc * CAP + t];
                                minAcc = fminf(minAcc,
                                    fmaf(m2x, tt.x,
                                    fmaf(m2y, tt.y,
                                    fmaf(m2z, tt.z, tt.w))));
                            }
                        }
                float edb = 3.4e38f;
                if (ex0 > 0)     edb = fminf(edb, qx - (float)ex0 * h);
                if (ex1 < G - 1) edb = fminf(edb, (float)(ex1 + 1) * h - qx);
                if (ey0 > 0)     edb = fminf(edb, qy - (float)ey0 * h);
                if (ey1 < G - 1) edb = fminf(edb, (float)(ey1 + 1) * h - qy);
                if (ez0 > 0)     edb = fminf(edb, qz - (float)ez0 * h);
                if (ez1 < G - 1) edb = fminf(edb, (float)(ez1 + 1) * h - qz);
                const bool ef = (ex0 == 0 && ey0 == 0 && ez0 == 0 &&
                                 ex1 == G - 1 && ey1 == G - 1 && ez1 == G - 1);
                if (ef || (qn + minAcc) <= edb * edb) break;
                ++r;
            }
        }

        const float dist = fmaxf(qn + minAcc, 0.0f);
        if (dir == 0) acc0 = dist; else acc1 = dist;
    }

    // ---- deterministic per-block partials ----
    __shared__ float red0[BLK / 32], red1[BLK / 32];
    __shared__ bool  amLast;
#pragma unroll
    for (int o = 16; o > 0; o >>= 1) {
        acc0 += __shfl_xor_sync(0xffffffffu, acc0, o);
        acc1 += __shfl_xor_sync(0xffffffffu, acc1, o);
    }
    if ((threadIdx.x & 31) == 0) {
        red0[threadIdx.x >> 5] = acc0;
        red1[threadIdx.x >> 5] = acc1;
    }
    __syncthreads();
    if (threadIdx.x == 0) {
        float s0 = 0.f, s1 = 0.f;
#pragma unroll
        for (int w = 0; w < BLK / 32; ++w) { s0 += red0[w]; s1 += red1[w]; }
        const int bid = blockIdx.y * gridDim.x + blockIdx.x;
        g_p0[bid] = s0;
        g_p1[bid] = s1;
        __threadfence();                                    // release partials
        amLast = (atomicAdd(&g_done, 1u) == gridDim.x * gridDim.y - 1);
    }
    __syncthreads();

    // ---- last-arriving CTA: finalize + restore scratch ----
    if (amLast) {
        __threadfence();                                    // acquire partials
        const int nb = gridDim.x * gridDim.y;
        float s0 = 0.f, s1 = 0.f;
        for (int t = threadIdx.x; t < nb; t += BLK) {
            s0 += g_p0[t];
            s1 += g_p1[t];
        }
#pragma unroll
        for (int o = 16; o > 0; o >>= 1) {
            s0 += __shfl_xor_sync(0xffffffffu, s0, o);
            s1 += __shfl_xor_sync(0xffffffffu, s1, o);
        }
        if ((threadIdx.x & 31) == 0) {
            red0[threadIdx.x >> 5] = s0;
            red1[threadIdx.x >> 5] = s1;
        }
        __syncthreads();

        // restore scratch for next graph replay
        {
            const int nsets = 2 * B;
            int4* cp = (int4*)g_cnt;
            int4* np = (int4*)g_nbcnt;
            const int n4 = (nsets * NC) >> 2;
            for (int t = threadIdx.x; t < n4; t += BLK) {
                cp[t] = make_int4(0, 0, 0, 0);
                np[t] = make_int4(0, 0, 0, 0);
            }
            if (threadIdx.x < NSETS_MAX) g_ovf_cnt[threadIdx.x] = 0;
        }

        if (threadIdx.x == 0) {
            float t0 = 0.f, t1 = 0.f;
#pragma unroll
            for (int w = 0; w < BLK / 32; ++w) { t0 += red0[w]; t1 += red1[w]; }
            g_done = 0;
            const float rec = t0 / (float)((size_t)B * N) + t1 / (float)((size_t)B * M);
            for (int t = 0; t < out_size; ++t) out[t] = rec;  // (loss, rec_loss)
        }
    }
}

extern "C" void kernel_launch(void* const* d_in, const int* in_sizes, int n_in,
                              void* d_out, int out_size) {
    const float* pos  = (const float*)d_in[0];
    const float* xhat = (const float*)d_in[1];

    const int B = 2;
    const int N = in_sizes[0] / (B * 3);
    const int M = in_sizes[1] / (B * 3);
    const int nsets = 2 * B;
    const int maxP  = (N > M) ? N : M;
    const int nbx   = (maxP + BLK - 1) / BLK;

    {   // K1: one thread per (point, neighbor-offset)
        dim3 g(nbx, nsets, 27);
        insert27_kernel<<<g, BLK>>>(pos, xhat, N, M, B);
    }
    {   // K2: one thread per query (+fused finalize)
        dim3 g(nbx, nsets);
        query_kernel<<<g, BLK>>>(pos, xhat, (float*)d_out, out_size, N, M, B);
    }
}

// round 14
// speedup vs baseline: 1.4102x; 1.0299x over previous
#include <cuda_runtime.h>
#include <cuda_bf16.h>

// Chamfer distance via PRE-GATHERED neighborhood lists — 2 kernels.
// B=2, N=M=8192, C=3, coords ~U[0,1).
//
//  K1 insert27: each (point, one of its <=27 in-bounds neighbor cells) pair is
//     one thread: 1 atomic + 1 st.128 into that cell's NEIGHBORHOOD list.
//     The s==13 (center) copy also maintains the base per-cell list used by
//     the rare expansion fallback. Overflows -> per-set list.
//  K2 query: one thread per query. Load q, ONE count, then STREAM the
//     cell's neighborhood list (contiguous float4s, affine addresses, high
//     MLP) + (normally empty) overflow list. r=1 bound check; rare miss ->
//     serial ring expansion over base cells. Register-accumulate direction
//     sums; per-CTA partials; last-arriving CTA finalizes + re-zeros counts.
//
// Determinism: fixed thread->query mapping; fixed-order sums; atomic slot
// permutations only feed fminf (permutation-invariant) -> bitwise
// deterministic. Scratch (counts, overflow, done) restored every run ->
// graph-replay invariant.

#define G        16
#define NC       (G * G * G)
#define CAP      16            // base per-cell capacity (fallback path)
#define CAP2     112           // neighborhood list capacity (~54 expected)
#define OVF_CAP  256
#define B_MAX    4
#define NSETS_MAX 8
#define BLK      128
#define MAXBLK   4096

__device__ int    g_cnt  [NSETS_MAX * NC];                 // static zero; restored
__device__ float4 g_cell [NSETS_MAX * NC * CAP];
__device__ int    g_nbcnt[NSETS_MAX * NC];                 // static zero; restored
__device__ float4 g_nb   [NSETS_MAX * NC * CAP2];          // ~59MB static
__device__ int    g_ovf_cnt[NSETS_MAX];                    // static zero; restored
__device__ float4 g_ovf  [NSETS_MAX * OVF_CAP];
__device__ float  g_p0[MAXBLK], g_p1[MAXBLK];
__device__ unsigned int g_done = 0;

__device__ __forceinline__ int cell_of(float v) {
    int c = (int)(v * (float)G);
    return min(max(c, 0), G - 1);
}

// grid: (ceil(maxP/BLK), nsets, 27)
__global__ __launch_bounds__(BLK)
void insert27_kernel(const float* __restrict__ pos,
                     const float* __restrict__ xhat,
                     int N, int M, int B) {
    const int sid   = blockIdx.y;
    const int s     = blockIdx.z;               // neighbor offset id 0..26
    const int cloud = sid / B;
    const int b     = sid % B;
    const int n     = cloud ? M : N;
    const int i     = blockIdx.x * BLK + threadIdx.x;
    if (i >= n) return;

    const float* p = (cloud ? xhat : pos) + ((size_t)b * n + i) * 3;
    const float x = p[0], y = p[1], z = p[2];
    const int cx = cell_of(x), cy = cell_of(y), cz = cell_of(z);

    const int tx = cx + (s % 3) - 1;
    const int ty = cy + ((s / 3) % 3) - 1;
    const int tz = cz + (s / 9) - 1;

    const float4 v = make_float4(x, y, z, x * x + y * y + z * z);

    if (s == 13) {   // center copy: maintain base per-cell list for fallback
        const int c = (cz * G + cy) * G + cx;
        const int slot = atomicAdd(&g_cnt[sid * NC + c], 1);
        if (slot < CAP) {
            g_cell[(sid * NC + c) * CAP + slot] = v;
        } else {
            const int o = atomicAdd(&g_ovf_cnt[sid], 1);
            if (o < OVF_CAP) g_ovf[sid * OVF_CAP + o] = v;
        }
    }

    if (tx < 0 || tx >= G || ty < 0 || ty >= G || tz < 0 || tz >= G) return;
    const int c = (tz * G + ty) * G + tx;
    const int slot = atomicAdd(&g_nbcnt[sid * NC + c], 1);
    if (slot < CAP2) {
        g_nb[((size_t)(sid * NC + c)) * CAP2 + slot] = v;
    } else {
        const int o = atomicAdd(&g_ovf_cnt[sid], 1);
        if (o < OVF_CAP) g_ovf[sid * OVF_CAP + o] = v;
    }
}

// grid: (ceil(maxP/BLK), nsets)   one thread per query; finalize fused
__global__ __launch_bounds__(BLK)
void query_kernel(const float* __restrict__ pos,
                  const float* __restrict__ xhat,
                  float* __restrict__ out, int out_size,
                  int N, int M, int B) {
    const int yb  = blockIdx.y;          // dir*B + b
    const int dir = yb / B;
    const int b   = yb % B;
    const int nQ  = dir ? M : N;
    const int i   = blockIdx.x * BLK + threadIdx.x;

    float acc0 = 0.f, acc1 = 0.f;

    if (i < nQ) {
        const int sid_t = (1 - dir) * B + b;   // target = other cloud

        const float* qp = (dir ? xhat : pos) + ((size_t)b * nQ + i) * 3;
        const float qx = qp[0], qy = qp[1], qz = qp[2];
        const float qn = qx * qx + qy * qy + qz * qz;
        const float m2x = -2.0f * qx, m2y = -2.0f * qy, m2z = -2.0f * qz;
        const int cx = cell_of(qx), cy = cell_of(qy), cz = cell_of(qz);
        const int c  = (cz * G + cy) * G + cx;

        // ---- stream the pre-gathered neighborhood list ----
        const int nc = min(g_nbcnt[sid_t * NC + c], CAP2);
        const float4* __restrict__ lst = g_nb + ((size_t)(sid_t * NC + c)) * CAP2;

        float mA = 3.4e38f, mB2 = 3.4e38f, mC = 3.4e38f, mD = 3.4e38f;
        int k = 0;
        for (; k + 4 <= nc; k += 4) {
            const float4 t0 = lst[k + 0];
            const float4 t1 = lst[k + 1];
            const float4 t2 = lst[k + 2];
            const float4 t3 = lst[k + 3];
            mA  = fminf(mA,  fmaf(m2x, t0.x, fmaf(m2y, t0.y, fmaf(m2z, t0.z, t0.w))));
            mB2 = fminf(mB2, fmaf(m2x, t1.x, fmaf(m2y, t1.y, fmaf(m2z, t1.z, t1.w))));
            mC  = fminf(mC,  fmaf(m2x, t2.x, fmaf(m2y, t2.y, fmaf(m2z, t2.z, t2.w))));
            mD  = fminf(mD,  fmaf(m2x, t3.x, fmaf(m2y, t3.y, fmaf(m2z, t3.z, t3.w))));
        }
        for (; k < nc; ++k) {
            const float4 t0 = lst[k];
            mA = fminf(mA, fmaf(m2x, t0.x, fmaf(m2y, t0.y, fmaf(m2z, t0.z, t0.w))));
        }
        float minAcc = fminf(fminf(mA, mB2), fminf(mC, mD));

        // ---- overflow list (normally empty) ----
        {
            const int no = min(g_ovf_cnt[sid_t], OVF_CAP);
            for (int t = 0; t < no; ++t) {
                const float4 tt = g_ovf[sid_t * OVF_CAP + t];
                minAcc = fminf(minAcc,
                    fmaf(m2x, tt.x, fmaf(m2y, tt.y, fmaf(m2z, tt.z, tt.w))));
            }
        }

        // ---- r=1 termination bound; rare miss -> serial expansion ----
        const float h = 1.0f / (float)G;
        const int x0 = max(cx - 1, 0), x1 = min(cx + 1, G - 1);
        const int y0 = max(cy - 1, 0), y1 = min(cy + 1, G - 1);
        const int z0 = max(cz - 1, 0), z1 = min(cz + 1, G - 1);
        float db = 3.4e38f;
        if (x0 > 0)     db = fminf(db, qx - (float)x0 * h);
        if (x1 < G - 1) db = fminf(db, (float)(x1 + 1) * h - qx);
        if (y0 > 0)     db = fminf(db, qy - (float)y0 * h);
        if (y1 < G - 1) db = fminf(db, (float)(y1 + 1) * h - qy);
        if (z0 > 0)     db = fminf(db, qz - (float)z0 * h);
        if (z1 < G - 1) db = fminf(db, (float)(z1 + 1) * h - qz);

        if ((qn + minAcc) > db * db) {
            const int*    __restrict__ cnt  = g_cnt  + sid_t * NC;
            const float4* __restrict__ cell = g_cell + (size_t)sid_t * NC * CAP;
            int r = 2;
            while (true) {
                const int ex0 = max(cx - r, 0), ex1 = min(cx + r, G - 1);
                const int ey0 = max(cy - r, 0), ey1 = min(cy + r, G - 1);
                const int ez0 = max(cz - r, 0), ez1 = min(cz + r, G - 1);
                for (int z = ez0; z <= ez1; ++z)
                    for (int y = ey0; y <= ey1; ++y)
                        for (int x = ex0; x <= ex1; ++x) {
                            const int cc = (z * G + y) * G + x;
                            const int n2 = min(cnt[cc], CAP);
                            for (int t = 0; t < n2; ++t) {
                                const float4 tt = cell[cc * CAP + t];
                                minAcc = fminf(minAcc,
                                    fmaf(m2x, tt.x,
                                    fmaf(m2y, tt.y,
                                    fmaf(m2z, tt.z, tt.w))));
                            }
                        }
                float edb = 3.4e38f;
                if (ex0 > 0)     edb = fminf(edb, qx - (float)ex0 * h);
                if (ex1 < G - 1) edb = fminf(edb, (float)(ex1 + 1) * h - qx);
                if (ey0 > 0)     edb = fminf(edb, qy - (float)ey0 * h);
                if (ey1 < G - 1) edb = fminf(edb, (float)(ey1 + 1) * h - qy);
                if (ez0 > 0)     edb = fminf(edb, qz - (float)ez0 * h);
                if (ez1 < G - 1) edb = fminf(edb, (float)(ez1 + 1) * h - qz);
                const bool ef = (ex0 == 0 && ey0 == 0 && ez0 == 0 &&
                                 ex1 == G - 1 && ey1 == G - 1 && ez1 == G - 1);
                if (ef || (qn + minAcc) <= edb * edb) break;
                ++r;
            }
        }

        const float dist = fmaxf(qn + minAcc, 0.0f);
        if (dir == 0) acc0 = dist; else acc1 = dist;
    }

    // ---- deterministic per-block partials ----
    __shared__ float red0[BLK / 32], red1[BLK / 32];
    __shared__ bool  amLast;
#pragma unroll
    for (int o = 16; o > 0; o >>= 1) {
        acc0 += __shfl_xor_sync(0xffffffffu, acc0, o);
        acc1 += __shfl_xor_sync(0xffffffffu, acc1, o);
    }
    if ((threadIdx.x & 31) == 0) {
        red0[threadIdx.x >> 5] = acc0;
        red1[threadIdx.x >> 5] = acc1;
    }
    __syncthreads();
    if (threadIdx.x == 0) {
        float s0 = 0.f, s1 = 0.f;
#pragma unroll
        for (int w = 0; w < BLK / 32; ++w) { s0 += red0[w]; s1 += red1[w]; }
        const int bid = blockIdx.y * gridDim.x + blockIdx.x;
        g_p0[bid] = s0;
        g_p1[bid] = s1;
        __threadfence();                                    // release partials
        amLast = (atomicAdd(&g_done, 1u) == gridDim.x * gridDim.y - 1);
    }
    __syncthreads();

    // ---- last-arriving CTA: finalize + restore scratch ----
    if (amLast) {
        __threadfence();                                    // acquire partials
        const int nb = gridDim.x * gridDim.y;
        float s0 = 0.f, s1 = 0.f;
        for (int t = threadIdx.x; t < nb; t += BLK) {
            s0 += g_p0[t];
            s1 += g_p1[t];
        }
#pragma unroll
        for (int o = 16; o > 0; o >>= 1) {
            s0 += __shfl_xor_sync(0xffffffffu, s0, o);
            s1 += __shfl_xor_sync(0xffffffffu, s1, o);
        }
        if ((threadIdx.x & 31) == 0) {
            red0[threadIdx.x >> 5] = s0;
            red1[threadIdx.x >> 5] = s1;
        }
        __syncthreads();

        // restore scratch for next graph replay
        {
            const int nsets = 2 * B;
            int4* cp = (int4*)g_cnt;
            int4* np = (int4*)g_nbcnt;
            const int n4 = (nsets * NC) >> 2;
            for (int t = threadIdx.x; t < n4; t += BLK) {
                cp[t] = make_int4(0, 0, 0, 0);
                np[t] = make_int4(0, 0, 0, 0);
            }
            if (threadIdx.x < NSETS_MAX) g_ovf_cnt[threadIdx.x] = 0;
        }

        if (threadIdx.x == 0) {
            float t0 = 0.f, t1 = 0.f;
#pragma unroll
            for (int w = 0; w < BLK / 32; ++w) { t0 += red0[w]; t1 += red1[w]; }
            g_done = 0;
            const float rec = t0 / (float)((size_t)B * N) + t1 / (float)((size_t)B * M);
            for (int t = 0; t < out_size; ++t) out[t] = rec;  // (loss, rec_loss)
        }
    }
}

extern "C" void kernel_launch(void* const* d_in, const int* in_sizes, int n_in,
                              void* d_out, int out_size) {
    const float* pos  = (const float*)d_in[0];
    const float* xhat = (const float*)d_in[1];

    const int B = 2;
    const int N = in_sizes[0] / (B * 3);
    const int M = in_sizes[1] / (B * 3);
    const int nsets = 2 * B;
    const int maxP  = (N > M) ? N : M;
    const int nbx   = (maxP + BLK - 1) / BLK;

    {   // K1: one thread per (point, neighbor-offset)
        dim3 g(nbx, nsets, 27);
        insert27_kernel<<<g, BLK>>>(pos, xhat, N, M, B);
    }
    {   // K2: one thread per query (+fused finalize)
        dim3 g(nbx, nsets);
        query_kernel<<<g, BLK>>>(pos, xhat, (float*)d_out, out_size, N, M, B);
    }
}